// round 7
// baseline (speedup 1.0000x reference)
#include <cuda_runtime.h>
#include <cuda_bf16.h>
#include <stdint.h>

// MSRSA fused attention — flash-style single-pass bf16x3 mma.sync kernel.
// B=2, H=16, L=2048, D=128.
// QT=64 rows/CTA, KTILE=32 (smem 111KB -> 2 CTAs/SM). One pass over K:
// logits(mma) -> modulate -> exp(l-16) -> attn store (unnormalized) ->
// PV(mma). Tail: CTA rescales its own attn block in place (overlaps with
// the co-resident CTA's tensor work at occupancy 2).

#define Bq 2
#define Hh 16
#define Ll 2048
#define Dd 128
#define QT 64
#define KTILE 32
#define NKT 64
#define NTHREADS 256
#define INV_SCALE 0.08838834764831845f   // 1/sqrt(128)
#define EXP_OFF 16.0f

// smem layout (bytes)
#define QPB 272                  // Q plane row pitch (136 bf16)
#define KPB 272                  // K plane row pitch
#define VPB 80                   // V^T plane row pitch (32 k * 2B + 16 pad)
#define Q_PLANE (64 * QPB)       // 17408
#define K_PLANE (KTILE * KPB)    // 8704
#define V_PLANE (128 * VPB)      // 10240
#define SM_Q 0
#define SM_STG (2 * Q_PLANE)     // 34816
#define STG_V (2 * K_PLANE)      // 17408 (V planes offset within stage)
#define STG_SIZE (2 * K_PLANE + 2 * V_PLANE)   // 37888
#define SM_ROWSUM (SM_STG + 2 * STG_SIZE)      // 110592
#define SM_INV (SM_ROWSUM + 512)               // 111104
#define SM_RED SM_STG            // reuse stage area after main loop
#define RED_PITCH 132
#define SMEM_TOTAL (SM_INV + 256 + 16)         // 111376  (x2 = 222752 <= 228KB/SM)

#define NELEM ((size_t)Bq * Hh * Ll * Dd)

__device__ __nv_bfloat16 g_Khi[NELEM];
__device__ __nv_bfloat16 g_Klo[NELEM];
__device__ __nv_bfloat16 g_Vthi[NELEM];   // [bh][d][k]
__device__ __nv_bfloat16 g_Vtlo[NELEM];

// ---------------- helpers ----------------
__device__ __forceinline__ uint32_t s2u(const void* p) {
    return (uint32_t)__cvta_generic_to_shared(p);
}
__device__ __forceinline__ void cp16(uint32_t dst, const void* src) {
    asm volatile("cp.async.cg.shared.global [%0], [%1], 16;\n" :: "r"(dst), "l"(src));
}
__device__ __forceinline__ void ldsm4(uint32_t r[4], uint32_t addr) {
    asm volatile("ldmatrix.sync.aligned.m8n8.x4.shared.b16 {%0,%1,%2,%3}, [%4];\n"
                 : "=r"(r[0]), "=r"(r[1]), "=r"(r[2]), "=r"(r[3]) : "r"(addr));
}
__device__ __forceinline__ void mma16816(float c[4],
                                         uint32_t a0, uint32_t a1, uint32_t a2, uint32_t a3,
                                         uint32_t b0, uint32_t b1) {
    asm volatile(
        "mma.sync.aligned.m16n8k16.row.col.f32.bf16.bf16.f32 "
        "{%0,%1,%2,%3}, {%4,%5,%6,%7}, {%8,%9}, {%0,%1,%2,%3};\n"
        : "+f"(c[0]), "+f"(c[1]), "+f"(c[2]), "+f"(c[3])
        : "r"(a0), "r"(a1), "r"(a2), "r"(a3), "r"(b0), "r"(b1));
}
__device__ __forceinline__ void split2(float x, float y, uint32_t& hi, uint32_t& lo) {
    __nv_bfloat16 hx = __float2bfloat16_rn(x);
    __nv_bfloat16 hy = __float2bfloat16_rn(y);
    float rx = x - __bfloat162float(hx);
    float ry = y - __bfloat162float(hy);
    __nv_bfloat16 lx = __float2bfloat16_rn(rx);
    __nv_bfloat16 ly = __float2bfloat16_rn(ry);
    hi = (uint32_t)*(unsigned short*)&hx | ((uint32_t)*(unsigned short*)&hy << 16);
    lo = (uint32_t)*(unsigned short*)&lx | ((uint32_t)*(unsigned short*)&ly << 16);
}

// ---------------- prep kernels ----------------
__global__ void prep_k_kernel(const float* __restrict__ K) {
    size_t i = (size_t)blockIdx.x * blockDim.x + threadIdx.x;
    if (i >= NELEM / 4) return;
    float4 v = ((const float4*)K)[i];
    uint32_t h0, l0, h1, l1;
    split2(v.x, v.y, h0, l0);
    split2(v.z, v.w, h1, l1);
    ((uint2*)g_Khi)[i] = make_uint2(h0, h1);
    ((uint2*)g_Klo)[i] = make_uint2(l0, l1);
}

__global__ void prep_v_kernel(const float* __restrict__ V) {
    __shared__ float ts[32][33];
    const int tx = threadIdx.x, ty = threadIdx.y;    // (32, 8)
    const int k0 = blockIdx.x * 32;
    const int d0 = blockIdx.y * 32;
    const int bh = blockIdx.z;
    const size_t vb = (size_t)bh * Ll * Dd;
    #pragma unroll
    for (int i = 0; i < 4; ++i)
        ts[ty + 8 * i][tx] = V[vb + (size_t)(k0 + ty + 8 * i) * Dd + d0 + tx];
    __syncthreads();
    #pragma unroll
    for (int i = 0; i < 4; ++i) {
        float x = ts[tx][ty + 8 * i];
        __nv_bfloat16 h = __float2bfloat16_rn(x);
        __nv_bfloat16 l = __float2bfloat16_rn(x - __bfloat162float(h));
        size_t o = (size_t)bh * Dd * Ll + (size_t)(d0 + ty + 8 * i) * Ll + k0 + tx;
        g_Vthi[o] = h;
        g_Vtlo[o] = l;
    }
}

// ---------------- main kernel ----------------
__global__ void __launch_bounds__(NTHREADS, 2)
msrsa_flash_kernel(const float* __restrict__ Q,
                   const float* __restrict__ A,
                   const float* __restrict__ Dm,
                   const float* __restrict__ wA,
                   const float* __restrict__ wD,
                   float* __restrict__ out,
                   float* __restrict__ attn) {
    extern __shared__ char smc[];
    const uint32_t smb = s2u(smc);

    const int t = threadIdx.x;
    const int w = t >> 5;
    const int lane = t & 31;
    const int g = lane >> 2;
    const int tg = lane & 3;
    const int mg = w >> 1;        // 0..3  (m16 group)
    const int ng = w & 1;         // 0..1  (k16 chunk within tile)
    const int m0 = mg * 16;
    const int nbase = ng * 16;

    const int bx = blockIdx.x;
    const int h = bx & (Hh - 1);
    const int qt = (bx >> 4) & 31;
    const int b = bx >> 9;
    const int q0 = qt * QT;
    const size_t bh = (size_t)(b * Hh + h);

    const float wa = wA[h];
    const float wd = wD[h];
    const size_t kbase = bh * (size_t)Ll * Dd;
    const size_t vbase = bh * (size_t)Dd * Ll;

    // ---- fill Q planes (hi/lo, pair-packed) ----
    {
        const float* Qb = Q + (bh * Ll + q0) * Dd;
        #pragma unroll
        for (int i = 0; i < 16; ++i) {
            int idx = t + i * NTHREADS;          // 4096 pairs
            int row = idx >> 6, c = idx & 63;
            float2 v = *(const float2*)(Qb + row * Dd + 2 * c);
            uint32_t hi, lo;
            split2(v.x, v.y, hi, lo);
            *(uint32_t*)(smc + SM_Q + row * QPB + c * 4) = hi;
            *(uint32_t*)(smc + SM_Q + Q_PLANE + row * QPB + c * 4) = lo;
        }
    }

    // ---- stage issue (cp.async, one commit group per tile) ----
    auto issue_stage = [&](int kt, int buf) {
        const uint32_t sb = smb + SM_STG + buf * STG_SIZE;
        const char* gkh = (const char*)(g_Khi + kbase + (size_t)kt * KTILE * Dd);
        const char* gkl = (const char*)(g_Klo + kbase + (size_t)kt * KTILE * Dd);
        #pragma unroll
        for (int j = 0; j < 2; ++j) {
            int idx = t + j * NTHREADS;          // 512 chunks per plane
            int row = idx >> 4, ch = idx & 15;
            cp16(sb + row * KPB + ch * 16, gkh + row * 256 + ch * 16);
            cp16(sb + K_PLANE + row * KPB + ch * 16, gkl + row * 256 + ch * 16);
        }
        const char* gvh = (const char*)(g_Vthi + vbase) + (size_t)kt * (KTILE * 2);
        const char* gvl = (const char*)(g_Vtlo + vbase) + (size_t)kt * (KTILE * 2);
        #pragma unroll
        for (int j = 0; j < 2; ++j) {
            int idx = t + j * NTHREADS;          // 512 chunks per plane
            int d = idx >> 2, ch = idx & 3;
            cp16(sb + STG_V + d * VPB + ch * 16, gvh + (size_t)d * (Ll * 2) + ch * 16);
            cp16(sb + STG_V + V_PLANE + d * VPB + ch * 16, gvl + (size_t)d * (Ll * 2) + ch * 16);
        }
        asm volatile("cp.async.commit_group;\n" ::: "memory");
    };

    // ldmatrix lane offsets (bytes)
    const uint32_t a_off = (uint32_t)((m0 + (lane & 7) + ((lane >> 3) & 1) * 8) * QPB
                                      + (((lane >> 4) & 1) * 8) * 2);
    const uint32_t b_off = (uint32_t)((nbase + ((lane >> 4) << 3) + (lane & 7)) * KPB
                                      + (((lane >> 3) & 1) * 8) * 2);
    const uint32_t v_off = (uint32_t)((((lane >> 4) << 3) + (lane & 7)) * VPB
                                      + (nbase + ((lane >> 3) & 1) * 8) * 2);
    const uint32_t qh_base = smb + SM_Q;
    const uint32_t ql_base = qh_base + Q_PLANE;

    // per-warp global row pointers
    const float* Arow_lo = A  + ((size_t)b * Ll + q0 + m0 + g) * Ll;
    const float* Drow_lo = Dm + ((size_t)b * Ll + q0 + m0 + g) * Ll;
    float* attn_lo = attn + (bh * Ll + q0 + m0 + g) * Ll;

    float accO[16][4];
    #pragma unroll
    for (int i = 0; i < 16; ++i)
        #pragma unroll
        for (int j = 0; j < 4; ++j) accO[i][j] = 0.f;
    float rs_lo = 0.f, rs_hi = 0.f;

    issue_stage(0, 0);

    for (int kt = 0; kt < NKT; ++kt) {
        asm volatile("cp.async.wait_group 0;\n" ::: "memory");
        __syncthreads();
        if (kt + 1 < NKT) issue_stage(kt + 1, (kt + 1) & 1);

        const uint32_t kh = smb + SM_STG + (kt & 1) * STG_SIZE;
        const uint32_t kl = kh + K_PLANE;
        const uint32_t vh = kh + STG_V;
        const uint32_t vl = vh + V_PLANE;

        // ---- logits: m16 x n16 x d128 ----
        float c[2][4];
        #pragma unroll
        for (int i = 0; i < 2; ++i)
            #pragma unroll
            for (int j = 0; j < 4; ++j) c[i][j] = 0.f;

        #pragma unroll
        for (int s = 0; s < 8; ++s) {
            uint32_t ah[4], al[4], bh0[4], bl0[4];
            ldsm4(ah, qh_base + a_off + s * 32);
            ldsm4(al, ql_base + a_off + s * 32);
            ldsm4(bh0, kh + b_off + s * 32);
            ldsm4(bl0, kl + b_off + s * 32);
            #pragma unroll
            for (int j = 0; j < 2; ++j) {
                const int ii = j * 2;
                mma16816(c[j], ah[0], ah[1], ah[2], ah[3], bh0[ii], bh0[ii + 1]);
                mma16816(c[j], ah[0], ah[1], ah[2], ah[3], bl0[ii], bl0[ii + 1]);
                mma16816(c[j], al[0], al[1], al[2], al[3], bh0[ii], bh0[ii + 1]);
            }
        }

        // ---- modulate + exp + attn store + pack P fragments ----
        uint32_t pa_h[4], pa_l[4];
        #pragma unroll
        for (int j = 0; j < 2; ++j) {
            const int col = kt * KTILE + nbase + j * 8 + 2 * tg;
            float2 a0 = *(const float2*)(Arow_lo + col);
            float2 d0 = *(const float2*)(Drow_lo + col);
            float2 a1 = *(const float2*)(Arow_lo + 8 * Ll + col);
            float2 d1 = *(const float2*)(Drow_lo + 8 * Ll + col);
            float p00 = __expf(c[j][0] * ((1.f + a0.x * wa + d0.x * wd) * INV_SCALE) - EXP_OFF);
            float p01 = __expf(c[j][1] * ((1.f + a0.y * wa + d0.y * wd) * INV_SCALE) - EXP_OFF);
            float p10 = __expf(c[j][2] * ((1.f + a1.x * wa + d1.x * wd) * INV_SCALE) - EXP_OFF);
            float p11 = __expf(c[j][3] * ((1.f + a1.y * wa + d1.y * wd) * INV_SCALE) - EXP_OFF);
            *(float2*)(attn_lo + col) = make_float2(p00, p01);
            *(float2*)(attn_lo + 8 * Ll + col) = make_float2(p10, p11);
            rs_lo += p00 + p01;
            rs_hi += p10 + p11;
            const int ai = j * 2;
            split2(p00, p01, pa_h[ai], pa_l[ai]);
            split2(p10, p11, pa_h[ai + 1], pa_l[ai + 1]);
        }

        // ---- PV: A = P (m16 x k16), B = V^T (k16 x d128) ----
        #pragma unroll
        for (int q = 0; q < 8; ++q) {
            uint32_t vbh[4], vbl[4];
            const uint32_t voff = v_off + q * 16 * VPB;
            ldsm4(vbh, vh + voff);
            ldsm4(vbl, vl + voff);
            #pragma unroll
            for (int h2 = 0; h2 < 2; ++h2) {
                const int ni = q * 2 + h2;
                const int ii = h2 * 2;
                mma16816(accO[ni], pa_h[0], pa_h[1], pa_h[2], pa_h[3],
                         vbh[ii], vbh[ii + 1]);
                mma16816(accO[ni], pa_h[0], pa_h[1], pa_h[2], pa_h[3],
                         vbl[ii], vbl[ii + 1]);
                mma16816(accO[ni], pa_l[0], pa_l[1], pa_l[2], pa_l[3],
                         vbh[ii], vbh[ii + 1]);
            }
        }
    }

    // ---- rowsum reduce ----
    rs_lo += __shfl_xor_sync(0xffffffffu, rs_lo, 1);
    rs_lo += __shfl_xor_sync(0xffffffffu, rs_lo, 2);
    rs_hi += __shfl_xor_sync(0xffffffffu, rs_hi, 1);
    rs_hi += __shfl_xor_sync(0xffffffffu, rs_hi, 2);
    float* rsm = (float*)(smc + SM_ROWSUM);
    if (tg == 0) {
        rsm[(m0 + g) * 2 + ng] = rs_lo;
        rsm[(m0 + g + 8) * 2 + ng] = rs_hi;
    }
    __syncthreads();
    float* sinv = (float*)(smc + SM_INV);
    if (t < QT) {
        sinv[t] = 1.f / (rsm[t * 2] + rsm[t * 2 + 1]);
    }
    __syncthreads();

    // ---- PV cross-warp (ng) reduce + write out ----
    float* red = (float*)(smc + SM_RED) + mg * 16 * RED_PITCH;
    if (ng == 1) {
        #pragma unroll
        for (int ni = 0; ni < 16; ++ni) {
            const int col = ni * 8 + 2 * tg;
            *(float2*)&red[g * RED_PITCH + col] = make_float2(accO[ni][0], accO[ni][1]);
            *(float2*)&red[(g + 8) * RED_PITCH + col] = make_float2(accO[ni][2], accO[ni][3]);
        }
    }
    __syncthreads();
    if (ng == 0) {
        const float ivlo = sinv[m0 + g];
        const float ivhi = sinv[m0 + g + 8];
        float* olo = out + (bh * Ll + q0 + m0 + g) * Dd;
        #pragma unroll
        for (int ni = 0; ni < 16; ++ni) {
            const int col = ni * 8 + 2 * tg;
            float2 r0 = *(const float2*)&red[g * RED_PITCH + col];
            float2 r1 = *(const float2*)&red[(g + 8) * RED_PITCH + col];
            *(float2*)(olo + col) = make_float2((accO[ni][0] + r0.x) * ivlo,
                                                (accO[ni][1] + r0.y) * ivlo);
            *(float2*)(olo + 8 * Dd + col) = make_float2((accO[ni][2] + r1.x) * ivhi,
                                                         (accO[ni][3] + r1.y) * ivhi);
        }
    }

    // ---- in-place attn rescale (overlaps with co-resident CTA at occ 2) ----
    {
        float4* ab = (float4*)(attn + (bh * Ll + q0) * Ll);   // 64 rows x 512 float4
        #pragma unroll 4
        for (int i = 0; i < QT * Ll / 4 / NTHREADS; ++i) {
            const int idx = t + i * NTHREADS;
            const float iv = sinv[idx >> 9];
            float4 v = ab[idx];
            v.x *= iv; v.y *= iv; v.z *= iv; v.w *= iv;
            ab[idx] = v;
        }
    }
}

// ---------------- launch ----------------
extern "C" void kernel_launch(void* const* d_in, const int* in_sizes, int n_in,
                              void* d_out, int out_size) {
    (void)in_sizes; (void)n_in; (void)out_size;
    const float* Q  = (const float*)d_in[0];
    const float* K  = (const float*)d_in[1];
    const float* V  = (const float*)d_in[2];
    const float* A  = (const float*)d_in[3];
    const float* Ds = (const float*)d_in[4];
    const float* wA = (const float*)d_in[5];
    const float* wD = (const float*)d_in[6];

    float* out  = (float*)d_out;
    float* attn = (float*)d_out + (size_t)Bq * Hh * Ll * Dd;

    prep_k_kernel<<<(unsigned)(NELEM / 4 / 256), 256>>>(K);
    {
        dim3 gv(Ll / 32, Dd / 32, Bq * Hh);
        dim3 bv(32, 8);
        prep_v_kernel<<<gv, bv>>>(V);
    }

    cudaFuncSetAttribute(msrsa_flash_kernel,
                         cudaFuncAttributeMaxDynamicSharedMemorySize, SMEM_TOTAL);
    dim3 grid(Bq * Hh * (Ll / QT));   // 1024 CTAs, h innermost
    msrsa_flash_kernel<<<grid, NTHREADS, SMEM_TOTAL>>>(Q, A, Ds, wA, wD, out, attn);
}

// round 9
// speedup vs baseline: 1.6000x; 1.6000x over previous
#include <cuda_runtime.h>
#include <cuda_fp16.h>
#include <cuda_bf16.h>
#include <stdint.h>

// MSRSA fused attention — flash-style single-pass hybrid-precision kernel.
// B=2, H=16, L=2048, D=128.
// QK: fp16, Q split hi/lo, K hi-only  -> 2 mma per k16 (q * k_fp16).
// PV: bf16 3-term (P hi/lo, V hi/lo)  -> proven accurate, range-safe.
// QT=64 rows/CTA, KTILE=64, one pass over K. attn written unnormalized;
// separate DRAM-roofline rescale kernel divides by rowsum.

#define Bq 2
#define Hh 16
#define Ll 2048
#define Dd 128
#define QT 64
#define KTILE 64
#define NKT 32
#define NTHREADS 256
#define INV_SCALE 0.08838834764831845f   // 1/sqrt(128)
#define EXP_OFF 16.0f

// smem layout (bytes)
#define QPB 272                  // Q plane row pitch (136 halfwords)
#define KPB 272
#define VPB 144                  // V^T plane row pitch (72 bf16)
#define Q_PLANE (64 * QPB)       // 17408 (fp16 hi + lo planes)
#define K_PLANE (64 * KPB)       // 17408 (fp16 hi only)
#define V_PLANE (128 * VPB)      // 18432 (bf16 hi + lo)
#define SM_Q 0
#define SM_STG (2 * Q_PLANE)     // 34816
#define STG_V K_PLANE            // V planes offset within stage
#define STG_SIZE (K_PLANE + 2 * V_PLANE)       // 54272
#define SM_ROWSUM (SM_STG + 2 * STG_SIZE)      // 143360
#define SM_INV (SM_ROWSUM + 512)               // 143872
#define SM_RED SM_STG            // reuse stage area after main loop
#define RED_PITCH 132
#define SMEM_TOTAL (SM_INV + 256 + 16)         // 144144

#define NELEM ((size_t)Bq * Hh * Ll * Dd)

__device__ __half g_Kh[NELEM];            // fp16 hi only
__device__ __nv_bfloat16 g_Vthi[NELEM];   // [bh][d][k] bf16 hi
__device__ __nv_bfloat16 g_Vtlo[NELEM];   // [bh][d][k] bf16 lo
__device__ float g_inv[(size_t)Bq * Hh * Ll];

// ---------------- helpers ----------------
__device__ __forceinline__ uint32_t s2u(const void* p) {
    return (uint32_t)__cvta_generic_to_shared(p);
}
__device__ __forceinline__ void cp16(uint32_t dst, const void* src) {
    asm volatile("cp.async.cg.shared.global [%0], [%1], 16;\n" :: "r"(dst), "l"(src));
}
__device__ __forceinline__ void ldsm4(uint32_t r[4], uint32_t addr) {
    asm volatile("ldmatrix.sync.aligned.m8n8.x4.shared.b16 {%0,%1,%2,%3}, [%4];\n"
                 : "=r"(r[0]), "=r"(r[1]), "=r"(r[2]), "=r"(r[3]) : "r"(addr));
}
__device__ __forceinline__ void mma_f16(float c[4],
                                        uint32_t a0, uint32_t a1, uint32_t a2, uint32_t a3,
                                        uint32_t b0, uint32_t b1) {
    asm volatile(
        "mma.sync.aligned.m16n8k16.row.col.f32.f16.f16.f32 "
        "{%0,%1,%2,%3}, {%4,%5,%6,%7}, {%8,%9}, {%0,%1,%2,%3};\n"
        : "+f"(c[0]), "+f"(c[1]), "+f"(c[2]), "+f"(c[3])
        : "r"(a0), "r"(a1), "r"(a2), "r"(a3), "r"(b0), "r"(b1));
}
__device__ __forceinline__ void mma_bf16(float c[4],
                                         uint32_t a0, uint32_t a1, uint32_t a2, uint32_t a3,
                                         uint32_t b0, uint32_t b1) {
    asm volatile(
        "mma.sync.aligned.m16n8k16.row.col.f32.bf16.bf16.f32 "
        "{%0,%1,%2,%3}, {%4,%5,%6,%7}, {%8,%9}, {%0,%1,%2,%3};\n"
        : "+f"(c[0]), "+f"(c[1]), "+f"(c[2]), "+f"(c[3])
        : "r"(a0), "r"(a1), "r"(a2), "r"(a3), "r"(b0), "r"(b1));
}
__device__ __forceinline__ void split2h(float x, float y, uint32_t& hi, uint32_t& lo) {
    __half hx = __float2half_rn(x);
    __half hy = __float2half_rn(y);
    float rx = x - __half2float(hx);
    float ry = y - __half2float(hy);
    __half lx = __float2half_rn(rx);
    __half ly = __float2half_rn(ry);
    hi = (uint32_t)*(unsigned short*)&hx | ((uint32_t)*(unsigned short*)&hy << 16);
    lo = (uint32_t)*(unsigned short*)&lx | ((uint32_t)*(unsigned short*)&ly << 16);
}
__device__ __forceinline__ void split2b(float x, float y, uint32_t& hi, uint32_t& lo) {
    __nv_bfloat16 hx = __float2bfloat16_rn(x);
    __nv_bfloat16 hy = __float2bfloat16_rn(y);
    float rx = x - __bfloat162float(hx);
    float ry = y - __bfloat162float(hy);
    __nv_bfloat16 lx = __float2bfloat16_rn(rx);
    __nv_bfloat16 ly = __float2bfloat16_rn(ry);
    hi = (uint32_t)*(unsigned short*)&hx | ((uint32_t)*(unsigned short*)&hy << 16);
    lo = (uint32_t)*(unsigned short*)&lx | ((uint32_t)*(unsigned short*)&ly << 16);
}

// ---------------- prep kernels ----------------
__global__ void prep_k_kernel(const float* __restrict__ K) {
    size_t i = (size_t)blockIdx.x * blockDim.x + threadIdx.x;
    if (i >= NELEM / 4) return;
    float4 v = ((const float4*)K)[i];
    __half h0 = __float2half_rn(v.x), h1 = __float2half_rn(v.y);
    __half h2 = __float2half_rn(v.z), h3 = __float2half_rn(v.w);
    uint32_t w0 = (uint32_t)*(unsigned short*)&h0 | ((uint32_t)*(unsigned short*)&h1 << 16);
    uint32_t w1 = (uint32_t)*(unsigned short*)&h2 | ((uint32_t)*(unsigned short*)&h3 << 16);
    ((uint2*)g_Kh)[i] = make_uint2(w0, w1);
}

__global__ void prep_v_kernel(const float* __restrict__ V) {
    __shared__ float ts[32][33];
    const int tx = threadIdx.x, ty = threadIdx.y;    // (32, 8)
    const int k0 = blockIdx.x * 32;
    const int d0 = blockIdx.y * 32;
    const int bh = blockIdx.z;
    const size_t vb = (size_t)bh * Ll * Dd;
    #pragma unroll
    for (int i = 0; i < 4; ++i)
        ts[ty + 8 * i][tx] = V[vb + (size_t)(k0 + ty + 8 * i) * Dd + d0 + tx];
    __syncthreads();
    #pragma unroll
    for (int i = 0; i < 4; ++i) {
        float x = ts[tx][ty + 8 * i];
        __nv_bfloat16 h = __float2bfloat16_rn(x);
        __nv_bfloat16 l = __float2bfloat16_rn(x - __bfloat162float(h));
        size_t o = (size_t)bh * Dd * Ll + (size_t)(d0 + ty + 8 * i) * Ll + k0 + tx;
        g_Vthi[o] = h;
        g_Vtlo[o] = l;
    }
}

// ---------------- main kernel ----------------
__global__ void __launch_bounds__(NTHREADS, 1)
msrsa_flash_kernel(const float* __restrict__ Q,
                   const float* __restrict__ A,
                   const float* __restrict__ Dm,
                   const float* __restrict__ wA,
                   const float* __restrict__ wD,
                   float* __restrict__ out,
                   float* __restrict__ attn) {
    extern __shared__ char smc[];
    const uint32_t smb = s2u(smc);

    const int t = threadIdx.x;
    const int w = t >> 5;
    const int lane = t & 31;
    const int g = lane >> 2;
    const int tg = lane & 3;
    const int mg = w >> 1;        // 0..3  (m16 group)
    const int ng = w & 1;         // 0..1  (n32 chunk)
    const int m0 = mg * 16;
    const int nbase = ng * 32;

    const int bx = blockIdx.x;
    const int h = bx & (Hh - 1);
    const int qt = (bx >> 4) & 31;
    const int b = bx >> 9;
    const int q0 = qt * QT;
    const size_t bh = (size_t)(b * Hh + h);

    const float wa = wA[h];
    const float wd = wD[h];
    const size_t kbase = bh * (size_t)Ll * Dd;
    const size_t vbase = bh * (size_t)Dd * Ll;

    // ---- fill Q planes (hi/lo fp16, pair-packed) ----
    {
        const float* Qb = Q + (bh * Ll + q0) * Dd;
        #pragma unroll
        for (int i = 0; i < 16; ++i) {
            int idx = t + i * NTHREADS;          // 4096 pairs
            int row = idx >> 6, c = idx & 63;
            float2 v = *(const float2*)(Qb + row * Dd + 2 * c);
            uint32_t hi, lo;
            split2h(v.x, v.y, hi, lo);
            *(uint32_t*)(smc + SM_Q + row * QPB + c * 4) = hi;
            *(uint32_t*)(smc + SM_Q + Q_PLANE + row * QPB + c * 4) = lo;
        }
    }

    // ---- stage issue (cp.async, one commit group per tile) ----
    auto issue_stage = [&](int kt, int buf) {
        const uint32_t sb = smb + SM_STG + buf * STG_SIZE;
        const char* gk = (const char*)(g_Kh + kbase + (size_t)kt * KTILE * Dd);
        #pragma unroll
        for (int j = 0; j < 4; ++j) {
            int idx = t + j * NTHREADS;          // 1024 chunks
            int row = idx >> 4, ch = idx & 15;
            cp16(sb + row * KPB + ch * 16, gk + row * 256 + ch * 16);
        }
        const char* gvh = (const char*)(g_Vthi + vbase) + (size_t)kt * 128;
        const char* gvl = (const char*)(g_Vtlo + vbase) + (size_t)kt * 128;
        #pragma unroll
        for (int j = 0; j < 4; ++j) {
            int idx = t + j * NTHREADS;          // 1024 chunks
            int d = idx >> 3, ch = idx & 7;
            cp16(sb + STG_V + d * VPB + ch * 16, gvh + (size_t)d * (Ll * 2) + ch * 16);
            cp16(sb + STG_V + V_PLANE + d * VPB + ch * 16, gvl + (size_t)d * (Ll * 2) + ch * 16);
        }
        asm volatile("cp.async.commit_group;\n" ::: "memory");
    };

    // ldmatrix lane offsets (bytes)
    const uint32_t a_off = (uint32_t)((m0 + (lane & 7) + ((lane >> 3) & 1) * 8) * QPB
                                      + (((lane >> 4) & 1) * 8) * 2);
    const uint32_t b_off0 = (uint32_t)((nbase + ((lane >> 4) << 3) + (lane & 7)) * KPB
                                       + (((lane >> 3) & 1) * 8) * 2);
    const uint32_t b_off1 = b_off0 + 16 * KPB;
    const uint32_t v_off = (uint32_t)((((lane >> 4) << 3) + (lane & 7)) * VPB
                                      + (nbase + ((lane >> 3) & 1) * 8) * 2);
    const uint32_t qh_base = smb + SM_Q;
    const uint32_t ql_base = qh_base + Q_PLANE;

    // per-warp global row pointers
    const float* Arow_lo = A  + ((size_t)b * Ll + q0 + m0 + g) * Ll;
    const float* Drow_lo = Dm + ((size_t)b * Ll + q0 + m0 + g) * Ll;
    float* attn_lo = attn + (bh * Ll + q0 + m0 + g) * Ll;

    float accO[16][4];
    #pragma unroll
    for (int i = 0; i < 16; ++i)
        #pragma unroll
        for (int j = 0; j < 4; ++j) accO[i][j] = 0.f;
    float rs_lo = 0.f, rs_hi = 0.f;

    issue_stage(0, 0);

    for (int kt = 0; kt < NKT; ++kt) {
        asm volatile("cp.async.wait_group 0;\n" ::: "memory");
        __syncthreads();
        if (kt + 1 < NKT) issue_stage(kt + 1, (kt + 1) & 1);

        const uint32_t kh = smb + SM_STG + (kt & 1) * STG_SIZE;
        const uint32_t vh = kh + STG_V;
        const uint32_t vl = vh + V_PLANE;

        // ---- logits: m16 x n32 x d128, fp16:  QK = (qh + ql) * kh ----
        float c[4][4];
        #pragma unroll
        for (int i = 0; i < 4; ++i)
            #pragma unroll
            for (int j = 0; j < 4; ++j) c[i][j] = 0.f;

        #pragma unroll
        for (int s = 0; s < 8; ++s) {
            uint32_t ah[4], al[4], bh0[4], bh1[4];
            ldsm4(ah, qh_base + a_off + s * 32);
            ldsm4(al, ql_base + a_off + s * 32);
            ldsm4(bh0, kh + b_off0 + s * 32);
            ldsm4(bh1, kh + b_off1 + s * 32);
            #pragma unroll
            for (int j = 0; j < 4; ++j) {
                const uint32_t* bhp = (j < 2) ? bh0 : bh1;
                const int ii = (j & 1) * 2;
                mma_f16(c[j], ah[0], ah[1], ah[2], ah[3], bhp[ii], bhp[ii + 1]);
                mma_f16(c[j], al[0], al[1], al[2], al[3], bhp[ii], bhp[ii + 1]);
            }
        }

        // ---- modulate + exp + attn store + pack P fragments (bf16) ----
        uint32_t pa_h[2][4], pa_l[2][4];
        #pragma unroll
        for (int j = 0; j < 4; ++j) {
            const int col = kt * KTILE + nbase + j * 8 + 2 * tg;
            float2 a0 = *(const float2*)(Arow_lo + col);
            float2 d0 = *(const float2*)(Drow_lo + col);
            float2 a1 = *(const float2*)(Arow_lo + 8 * Ll + col);
            float2 d1 = *(const float2*)(Drow_lo + 8 * Ll + col);
            float p00 = __expf(c[j][0] * ((1.f + a0.x * wa + d0.x * wd) * INV_SCALE) - EXP_OFF);
            float p01 = __expf(c[j][1] * ((1.f + a0.y * wa + d0.y * wd) * INV_SCALE) - EXP_OFF);
            float p10 = __expf(c[j][2] * ((1.f + a1.x * wa + d1.x * wd) * INV_SCALE) - EXP_OFF);
            float p11 = __expf(c[j][3] * ((1.f + a1.y * wa + d1.y * wd) * INV_SCALE) - EXP_OFF);
            *(float2*)(attn_lo + col) = make_float2(p00, p01);
            *(float2*)(attn_lo + 8 * Ll + col) = make_float2(p10, p11);
            rs_lo += p00 + p01;
            rs_hi += p10 + p11;
            const int kf = j >> 1, ai = (j & 1) * 2;
            split2b(p00, p01, pa_h[kf][ai], pa_l[kf][ai]);
            split2b(p10, p11, pa_h[kf][ai + 1], pa_l[kf][ai + 1]);
        }

        // ---- PV (bf16 3-term): A = P (m16 x k32), B = V^T (k32 x d128) ----
        #pragma unroll
        for (int kf = 0; kf < 2; ++kf) {
            #pragma unroll
            for (int q = 0; q < 8; ++q) {
                uint32_t vbh[4], vbl[4];
                const uint32_t voff = v_off + q * 16 * VPB + kf * 32;
                ldsm4(vbh, vh + voff);
                ldsm4(vbl, vl + voff);
                #pragma unroll
                for (int h2 = 0; h2 < 2; ++h2) {
                    const int ni = q * 2 + h2;
                    const int ii = h2 * 2;
                    mma_bf16(accO[ni], pa_h[kf][0], pa_h[kf][1], pa_h[kf][2], pa_h[kf][3],
                             vbh[ii], vbh[ii + 1]);
                    mma_bf16(accO[ni], pa_h[kf][0], pa_h[kf][1], pa_h[kf][2], pa_h[kf][3],
                             vbl[ii], vbl[ii + 1]);
                    mma_bf16(accO[ni], pa_l[kf][0], pa_l[kf][1], pa_l[kf][2], pa_l[kf][3],
                             vbh[ii], vbh[ii + 1]);
                }
            }
        }
    }

    // ---- rowsum reduce ----
    rs_lo += __shfl_xor_sync(0xffffffffu, rs_lo, 1);
    rs_lo += __shfl_xor_sync(0xffffffffu, rs_lo, 2);
    rs_hi += __shfl_xor_sync(0xffffffffu, rs_hi, 1);
    rs_hi += __shfl_xor_sync(0xffffffffu, rs_hi, 2);
    float* rsm = (float*)(smc + SM_ROWSUM);
    if (tg == 0) {
        rsm[(m0 + g) * 2 + ng] = rs_lo;
        rsm[(m0 + g + 8) * 2 + ng] = rs_hi;
    }
    __syncthreads();
    float* sinv = (float*)(smc + SM_INV);
    if (t < QT) {
        float iv = 1.f / (rsm[t * 2] + rsm[t * 2 + 1]);
        sinv[t] = iv;
        g_inv[bh * Ll + q0 + t] = iv;
    }
    __syncthreads();

    // ---- PV cross-warp (ng) reduce + write out ----
    float* red = (float*)(smc + SM_RED) + mg * 16 * RED_PITCH;
    if (ng == 1) {
        #pragma unroll
        for (int ni = 0; ni < 16; ++ni) {
            const int col = ni * 8 + 2 * tg;
            *(float2*)&red[g * RED_PITCH + col] = make_float2(accO[ni][0], accO[ni][1]);
            *(float2*)&red[(g + 8) * RED_PITCH + col] = make_float2(accO[ni][2], accO[ni][3]);
        }
    }
    __syncthreads();
    if (ng == 0) {
        const float ivlo = sinv[m0 + g];
        const float ivhi = sinv[m0 + g + 8];
        float* olo = out + (bh * Ll + q0 + m0 + g) * Dd;
        #pragma unroll
        for (int ni = 0; ni < 16; ++ni) {
            const int col = ni * 8 + 2 * tg;
            float2 r0 = *(const float2*)&red[g * RED_PITCH + col];
            float2 r1 = *(const float2*)&red[(g + 8) * RED_PITCH + col];
            *(float2*)(olo + col) = make_float2((accO[ni][0] + r0.x) * ivlo,
                                                (accO[ni][1] + r0.y) * ivlo);
            *(float2*)(olo + 8 * Dd + col) = make_float2((accO[ni][2] + r1.x) * ivhi,
                                                         (accO[ni][3] + r1.y) * ivhi);
        }
    }
}

// ---------------- rescale kernel (normalize attn) ----------------
__global__ void __launch_bounds__(256)
rescale_kernel(float* __restrict__ attn) {
    const size_t row = blockIdx.x;
    const float iv = g_inv[row];
    float4* p = (float4*)(attn + row * Ll);
    #pragma unroll
    for (int i = 0; i < 2; ++i) {
        int idx = threadIdx.x + i * 256;
        float4 v = p[idx];
        v.x *= iv; v.y *= iv; v.z *= iv; v.w *= iv;
        p[idx] = v;
    }
}

// ---------------- launch ----------------
extern "C" void kernel_launch(void* const* d_in, const int* in_sizes, int n_in,
                              void* d_out, int out_size) {
    (void)in_sizes; (void)n_in; (void)out_size;
    const float* Q  = (const float*)d_in[0];
    const float* K  = (const float*)d_in[1];
    const float* V  = (const float*)d_in[2];
    const float* A  = (const float*)d_in[3];
    const float* Ds = (const float*)d_in[4];
    const float* wA = (const float*)d_in[5];
    const float* wD = (const float*)d_in[6];

    float* out  = (float*)d_out;
    float* attn = (float*)d_out + (size_t)Bq * Hh * Ll * Dd;

    prep_k_kernel<<<(unsigned)(NELEM / 4 / 256), 256>>>(K);
    {
        dim3 gv(Ll / 32, Dd / 32, Bq * Hh);
        dim3 bv(32, 8);
        prep_v_kernel<<<gv, bv>>>(V);
    }

    cudaFuncSetAttribute(msrsa_flash_kernel,
                         cudaFuncAttributeMaxDynamicSharedMemorySize, SMEM_TOTAL);
    dim3 grid(Bq * Hh * (Ll / QT));   // 1024 CTAs, h innermost
    msrsa_flash_kernel<<<grid, NTHREADS, SMEM_TOTAL>>>(Q, A, Ds, wA, wD, out, attn);

    rescale_kernel<<<Bq * Hh * Ll, 256>>>(attn);
}

// round 10
// speedup vs baseline: 1.7788x; 1.1118x over previous
#include <cuda_runtime.h>
#include <cuda_fp16.h>
#include <cuda_bf16.h>
#include <stdint.h>

// MSRSA fused attention — flash-style single-pass hybrid-precision kernel.
// B=2, H=16, L=2048, D=128.
// QK: fp16 1-term (q and k both fp16; Q fragments held in registers).
// PV: bf16 3-term (P hi/lo, V hi/lo) — range-safe, proven accurate.
// QT=64 rows/CTA, KTILE=64, one pass over K. attn written unnormalized;
// separate DRAM-roofline rescale kernel divides by rowsum.

#define Bq 2
#define Hh 16
#define Ll 2048
#define Dd 128
#define QT 64
#define KTILE 64
#define NKT 32
#define NTHREADS 256
#define INV_SCALE 0.08838834764831845f   // 1/sqrt(128)
#define EXP_OFF 16.0f

// smem layout (bytes)
#define KPB 272                  // K tile row pitch
#define VPB 144                  // V^T plane row pitch (72 bf16)
#define K_PLANE (64 * KPB)       // 17408 (fp16)
#define V_PLANE (128 * VPB)      // 18432 (bf16 hi + lo)
#define SM_STG 0
#define STG_V K_PLANE            // V planes offset within stage
#define STG_SIZE (K_PLANE + 2 * V_PLANE)       // 54272
#define SM_ROWSUM (2 * STG_SIZE)               // 108544
#define SM_INV (SM_ROWSUM + 512)               // 109056
#define SM_RED SM_STG            // reuse stage area after main loop
#define RED_PITCH 132
#define SMEM_TOTAL (SM_INV + 256 + 16)         // 109328

#define NELEM ((size_t)Bq * Hh * Ll * Dd)

__device__ __half g_Kh[NELEM];            // fp16
__device__ __nv_bfloat16 g_Vthi[NELEM];   // [bh][d][k] bf16 hi
__device__ __nv_bfloat16 g_Vtlo[NELEM];   // [bh][d][k] bf16 lo
__device__ float g_inv[(size_t)Bq * Hh * Ll];

// ---------------- helpers ----------------
__device__ __forceinline__ uint32_t s2u(const void* p) {
    return (uint32_t)__cvta_generic_to_shared(p);
}
__device__ __forceinline__ void cp16(uint32_t dst, const void* src) {
    asm volatile("cp.async.cg.shared.global [%0], [%1], 16;\n" :: "r"(dst), "l"(src));
}
__device__ __forceinline__ void ldsm4(uint32_t r[4], uint32_t addr) {
    asm volatile("ldmatrix.sync.aligned.m8n8.x4.shared.b16 {%0,%1,%2,%3}, [%4];\n"
                 : "=r"(r[0]), "=r"(r[1]), "=r"(r[2]), "=r"(r[3]) : "r"(addr));
}
__device__ __forceinline__ void mma_f16(float c[4],
                                        uint32_t a0, uint32_t a1, uint32_t a2, uint32_t a3,
                                        uint32_t b0, uint32_t b1) {
    asm volatile(
        "mma.sync.aligned.m16n8k16.row.col.f32.f16.f16.f32 "
        "{%0,%1,%2,%3}, {%4,%5,%6,%7}, {%8,%9}, {%0,%1,%2,%3};\n"
        : "+f"(c[0]), "+f"(c[1]), "+f"(c[2]), "+f"(c[3])
        : "r"(a0), "r"(a1), "r"(a2), "r"(a3), "r"(b0), "r"(b1));
}
__device__ __forceinline__ void mma_bf16(float c[4],
                                         uint32_t a0, uint32_t a1, uint32_t a2, uint32_t a3,
                                         uint32_t b0, uint32_t b1) {
    asm volatile(
        "mma.sync.aligned.m16n8k16.row.col.f32.bf16.bf16.f32 "
        "{%0,%1,%2,%3}, {%4,%5,%6,%7}, {%8,%9}, {%0,%1,%2,%3};\n"
        : "+f"(c[0]), "+f"(c[1]), "+f"(c[2]), "+f"(c[3])
        : "r"(a0), "r"(a1), "r"(a2), "r"(a3), "r"(b0), "r"(b1));
}
__device__ __forceinline__ uint32_t packh2(float x, float y) {
    __half hx = __float2half_rn(x);
    __half hy = __float2half_rn(y);
    return (uint32_t)*(unsigned short*)&hx | ((uint32_t)*(unsigned short*)&hy << 16);
}
__device__ __forceinline__ void split2b(float x, float y, uint32_t& hi, uint32_t& lo) {
    __nv_bfloat16 hx = __float2bfloat16_rn(x);
    __nv_bfloat16 hy = __float2bfloat16_rn(y);
    float rx = x - __bfloat162float(hx);
    float ry = y - __bfloat162float(hy);
    __nv_bfloat16 lx = __float2bfloat16_rn(rx);
    __nv_bfloat16 ly = __float2bfloat16_rn(ry);
    hi = (uint32_t)*(unsigned short*)&hx | ((uint32_t)*(unsigned short*)&hy << 16);
    lo = (uint32_t)*(unsigned short*)&lx | ((uint32_t)*(unsigned short*)&ly << 16);
}

// ---------------- prep kernels ----------------
__global__ void prep_k_kernel(const float* __restrict__ K) {
    size_t i = (size_t)blockIdx.x * blockDim.x + threadIdx.x;
    if (i >= NELEM / 4) return;
    float4 v = ((const float4*)K)[i];
    ((uint2*)g_Kh)[i] = make_uint2(packh2(v.x, v.y), packh2(v.z, v.w));
}

__global__ void prep_v_kernel(const float* __restrict__ V) {
    __shared__ float ts[32][33];
    const int tx = threadIdx.x, ty = threadIdx.y;    // (32, 8)
    const int k0 = blockIdx.x * 32;
    const int d0 = blockIdx.y * 32;
    const int bh = blockIdx.z;
    const size_t vb = (size_t)bh * Ll * Dd;
    #pragma unroll
    for (int i = 0; i < 4; ++i)
        ts[ty + 8 * i][tx] = V[vb + (size_t)(k0 + ty + 8 * i) * Dd + d0 + tx];
    __syncthreads();
    #pragma unroll
    for (int i = 0; i < 4; ++i) {
        float x = ts[tx][ty + 8 * i];
        __nv_bfloat16 h = __float2bfloat16_rn(x);
        __nv_bfloat16 l = __float2bfloat16_rn(x - __bfloat162float(h));
        size_t o = (size_t)bh * Dd * Ll + (size_t)(d0 + ty + 8 * i) * Ll + k0 + tx;
        g_Vthi[o] = h;
        g_Vtlo[o] = l;
    }
}

// ---------------- main kernel ----------------
__global__ void __launch_bounds__(NTHREADS, 1)
msrsa_flash_kernel(const float* __restrict__ Q,
                   const float* __restrict__ A,
                   const float* __restrict__ Dm,
                   const float* __restrict__ wA,
                   const float* __restrict__ wD,
                   float* __restrict__ out,
                   float* __restrict__ attn) {
    extern __shared__ char smc[];
    const uint32_t smb = s2u(smc);

    const int t = threadIdx.x;
    const int w = t >> 5;
    const int lane = t & 31;
    const int g = lane >> 2;
    const int tg = lane & 3;
    const int mg = w >> 1;        // 0..3  (m16 group)
    const int ng = w & 1;         // 0..1  (n32 chunk)
    const int m0 = mg * 16;
    const int nbase = ng * 32;

    const int bx = blockIdx.x;
    const int h = bx & (Hh - 1);
    const int qt = (bx >> 4) & 31;
    const int b = bx >> 9;
    const int q0 = qt * QT;
    const size_t bh = (size_t)(b * Hh + h);

    const float wa = wA[h];
    const float wd = wD[h];
    const size_t kbase = bh * (size_t)Ll * Dd;
    const size_t vbase = bh * (size_t)Dd * Ll;

    // ---- Q fragments in registers (loop-invariant, fp16) ----
    uint32_t qf[8][4];
    {
        const float* Qb = Q + (bh * Ll + q0 + m0) * Dd;
        #pragma unroll
        for (int s = 0; s < 8; ++s) {
            const int c0 = 16 * s + 2 * tg;
            float2 p0 = *(const float2*)&Qb[g * Dd + c0];
            float2 p1 = *(const float2*)&Qb[(g + 8) * Dd + c0];
            float2 p2 = *(const float2*)&Qb[g * Dd + c0 + 8];
            float2 p3 = *(const float2*)&Qb[(g + 8) * Dd + c0 + 8];
            qf[s][0] = packh2(p0.x, p0.y);
            qf[s][1] = packh2(p1.x, p1.y);
            qf[s][2] = packh2(p2.x, p2.y);
            qf[s][3] = packh2(p3.x, p3.y);
        }
    }

    // ---- stage issue (cp.async, one commit group per tile) ----
    auto issue_stage = [&](int kt, int buf) {
        const uint32_t sb = smb + SM_STG + buf * STG_SIZE;
        const char* gk = (const char*)(g_Kh + kbase + (size_t)kt * KTILE * Dd);
        #pragma unroll
        for (int j = 0; j < 4; ++j) {
            int idx = t + j * NTHREADS;          // 1024 chunks
            int row = idx >> 4, ch = idx & 15;
            cp16(sb + row * KPB + ch * 16, gk + row * 256 + ch * 16);
        }
        const char* gvh = (const char*)(g_Vthi + vbase) + (size_t)kt * 128;
        const char* gvl = (const char*)(g_Vtlo + vbase) + (size_t)kt * 128;
        #pragma unroll
        for (int j = 0; j < 4; ++j) {
            int idx = t + j * NTHREADS;          // 1024 chunks
            int d = idx >> 3, ch = idx & 7;
            cp16(sb + STG_V + d * VPB + ch * 16, gvh + (size_t)d * (Ll * 2) + ch * 16);
            cp16(sb + STG_V + V_PLANE + d * VPB + ch * 16, gvl + (size_t)d * (Ll * 2) + ch * 16);
        }
        asm volatile("cp.async.commit_group;\n" ::: "memory");
    };

    // ldmatrix lane offsets (bytes)
    const uint32_t b_off0 = (uint32_t)((nbase + ((lane >> 4) << 3) + (lane & 7)) * KPB
                                       + (((lane >> 3) & 1) * 8) * 2);
    const uint32_t b_off1 = b_off0 + 16 * KPB;
    const uint32_t v_off = (uint32_t)((((lane >> 4) << 3) + (lane & 7)) * VPB
                                      + (nbase + ((lane >> 3) & 1) * 8) * 2);

    // per-warp global row pointers
    const float* Arow_lo = A  + ((size_t)b * Ll + q0 + m0 + g) * Ll;
    const float* Drow_lo = Dm + ((size_t)b * Ll + q0 + m0 + g) * Ll;
    float* attn_lo = attn + (bh * Ll + q0 + m0 + g) * Ll;

    float accO[16][4];
    #pragma unroll
    for (int i = 0; i < 16; ++i)
        #pragma unroll
        for (int j = 0; j < 4; ++j) accO[i][j] = 0.f;
    float rs_lo = 0.f, rs_hi = 0.f;

    issue_stage(0, 0);

    for (int kt = 0; kt < NKT; ++kt) {
        asm volatile("cp.async.wait_group 0;\n" ::: "memory");
        __syncthreads();
        if (kt + 1 < NKT) issue_stage(kt + 1, (kt + 1) & 1);

        const uint32_t kh = smb + SM_STG + (kt & 1) * STG_SIZE;
        const uint32_t vh = kh + STG_V;
        const uint32_t vl = vh + V_PLANE;

        // ---- logits: m16 x n32 x d128, fp16 1-term ----
        float c[4][4];
        #pragma unroll
        for (int i = 0; i < 4; ++i)
            #pragma unroll
            for (int j = 0; j < 4; ++j) c[i][j] = 0.f;

        #pragma unroll
        for (int s = 0; s < 8; ++s) {
            uint32_t bh0[4], bh1[4];
            ldsm4(bh0, kh + b_off0 + s * 32);
            ldsm4(bh1, kh + b_off1 + s * 32);
            #pragma unroll
            for (int j = 0; j < 4; ++j) {
                const uint32_t* bhp = (j < 2) ? bh0 : bh1;
                const int ii = (j & 1) * 2;
                mma_f16(c[j], qf[s][0], qf[s][1], qf[s][2], qf[s][3], bhp[ii], bhp[ii + 1]);
            }
        }

        // ---- modulate + exp + attn store + pack P fragments (bf16) ----
        uint32_t pa_h[2][4], pa_l[2][4];
        #pragma unroll
        for (int j = 0; j < 4; ++j) {
            const int col = kt * KTILE + nbase + j * 8 + 2 * tg;
            float2 a0 = *(const float2*)(Arow_lo + col);
            float2 d0 = *(const float2*)(Drow_lo + col);
            float2 a1 = *(const float2*)(Arow_lo + 8 * Ll + col);
            float2 d1 = *(const float2*)(Drow_lo + 8 * Ll + col);
            float p00 = __expf(c[j][0] * ((1.f + a0.x * wa + d0.x * wd) * INV_SCALE) - EXP_OFF);
            float p01 = __expf(c[j][1] * ((1.f + a0.y * wa + d0.y * wd) * INV_SCALE) - EXP_OFF);
            float p10 = __expf(c[j][2] * ((1.f + a1.x * wa + d1.x * wd) * INV_SCALE) - EXP_OFF);
            float p11 = __expf(c[j][3] * ((1.f + a1.y * wa + d1.y * wd) * INV_SCALE) - EXP_OFF);
            *(float2*)(attn_lo + col) = make_float2(p00, p01);
            *(float2*)(attn_lo + 8 * Ll + col) = make_float2(p10, p11);
            rs_lo += p00 + p01;
            rs_hi += p10 + p11;
            const int kf = j >> 1, ai = (j & 1) * 2;
            split2b(p00, p01, pa_h[kf][ai], pa_l[kf][ai]);
            split2b(p10, p11, pa_h[kf][ai + 1], pa_l[kf][ai + 1]);
        }

        // ---- PV (bf16 3-term): A = P (m16 x k32), B = V^T (k32 x d128) ----
        #pragma unroll
        for (int kf = 0; kf < 2; ++kf) {
            #pragma unroll
            for (int q = 0; q < 8; ++q) {
                uint32_t vbh[4], vbl[4];
                const uint32_t voff = v_off + q * 16 * VPB + kf * 32;
                ldsm4(vbh, vh + voff);
                ldsm4(vbl, vl + voff);
                #pragma unroll
                for (int h2 = 0; h2 < 2; ++h2) {
                    const int ni = q * 2 + h2;
                    const int ii = h2 * 2;
                    mma_bf16(accO[ni], pa_h[kf][0], pa_h[kf][1], pa_h[kf][2], pa_h[kf][3],
                             vbh[ii], vbh[ii + 1]);
                    mma_bf16(accO[ni], pa_h[kf][0], pa_h[kf][1], pa_h[kf][2], pa_h[kf][3],
                             vbl[ii], vbl[ii + 1]);
                    mma_bf16(accO[ni], pa_l[kf][0], pa_l[kf][1], pa_l[kf][2], pa_l[kf][3],
                             vbh[ii], vbh[ii + 1]);
                }
            }
        }
    }

    // ---- rowsum reduce ----
    rs_lo += __shfl_xor_sync(0xffffffffu, rs_lo, 1);
    rs_lo += __shfl_xor_sync(0xffffffffu, rs_lo, 2);
    rs_hi += __shfl_xor_sync(0xffffffffu, rs_hi, 1);
    rs_hi += __shfl_xor_sync(0xffffffffu, rs_hi, 2);
    float* rsm = (float*)(smc + SM_ROWSUM);
    if (tg == 0) {
        rsm[(m0 + g) * 2 + ng] = rs_lo;
        rsm[(m0 + g + 8) * 2 + ng] = rs_hi;
    }
    __syncthreads();
    float* sinv = (float*)(smc + SM_INV);
    if (t < QT) {
        float iv = 1.f / (rsm[t * 2] + rsm[t * 2 + 1]);
        sinv[t] = iv;
        g_inv[bh * Ll + q0 + t] = iv;
    }
    __syncthreads();

    // ---- PV cross-warp (ng) reduce + write out ----
    float* red = (float*)(smc + SM_RED) + mg * 16 * RED_PITCH;
    if (ng == 1) {
        #pragma unroll
        for (int ni = 0; ni < 16; ++ni) {
            const int col = ni * 8 + 2 * tg;
            *(float2*)&red[g * RED_PITCH + col] = make_float2(accO[ni][0], accO[ni][1]);
            *(float2*)&red[(g + 8) * RED_PITCH + col] = make_float2(accO[ni][2], accO[ni][3]);
        }
    }
    __syncthreads();
    if (ng == 0) {
        const float ivlo = sinv[m0 + g];
        const float ivhi = sinv[m0 + g + 8];
        float* olo = out + (bh * Ll + q0 + m0 + g) * Dd;
        #pragma unroll
        for (int ni = 0; ni < 16; ++ni) {
            const int col = ni * 8 + 2 * tg;
            float2 r0 = *(const float2*)&red[g * RED_PITCH + col];
            float2 r1 = *(const float2*)&red[(g + 8) * RED_PITCH + col];
            *(float2*)(olo + col) = make_float2((accO[ni][0] + r0.x) * ivlo,
                                                (accO[ni][1] + r0.y) * ivlo);
            *(float2*)(olo + 8 * Dd + col) = make_float2((accO[ni][2] + r1.x) * ivhi,
                                                         (accO[ni][3] + r1.y) * ivhi);
        }
    }
}

// ---------------- rescale kernel (normalize attn) ----------------
__global__ void __launch_bounds__(256)
rescale_kernel(float* __restrict__ attn) {
    const size_t row = blockIdx.x;
    const float iv = g_inv[row];
    float4* p = (float4*)(attn + row * Ll);
    #pragma unroll
    for (int i = 0; i < 2; ++i) {
        int idx = threadIdx.x + i * 256;
        float4 v = p[idx];
        v.x *= iv; v.y *= iv; v.z *= iv; v.w *= iv;
        p[idx] = v;
    }
}

// ---------------- launch ----------------
extern "C" void kernel_launch(void* const* d_in, const int* in_sizes, int n_in,
                              void* d_out, int out_size) {
    (void)in_sizes; (void)n_in; (void)out_size;
    const float* Q  = (const float*)d_in[0];
    const float* K  = (const float*)d_in[1];
    const float* V  = (const float*)d_in[2];
    const float* A  = (const float*)d_in[3];
    const float* Ds = (const float*)d_in[4];
    const float* wA = (const float*)d_in[5];
    const float* wD = (const float*)d_in[6];

    float* out  = (float*)d_out;
    float* attn = (float*)d_out + (size_t)Bq * Hh * Ll * Dd;

    prep_k_kernel<<<(unsigned)(NELEM / 4 / 256), 256>>>(K);
    {
        dim3 gv(Ll / 32, Dd / 32, Bq * Hh);
        dim3 bv(32, 8);
        prep_v_kernel<<<gv, bv>>>(V);
    }

    cudaFuncSetAttribute(msrsa_flash_kernel,
                         cudaFuncAttributeMaxDynamicSharedMemorySize, SMEM_TOTAL);
    dim3 grid(Bq * Hh * (Ll / QT));   // 1024 CTAs, h innermost
    msrsa_flash_kernel<<<grid, NTHREADS, SMEM_TOTAL>>>(Q, A, Ds, wA, wD, out, attn);

    rescale_kernel<<<Bq * Hh * Ll, 256>>>(attn);
}

// round 11
// speedup vs baseline: 2.0047x; 1.1270x over previous
#include <cuda_runtime.h>
#include <cuda_fp16.h>
#include <cuda_bf16.h>
#include <stdint.h>

// MSRSA fused attention — flash-style single-pass fp16 kernel with online
// row-max. B=2, H=16, L=2048, D=128.
// QK: fp16 1-term (Q frags in registers, K fp16).
// PV: fp16 1-term; P = exp(l - running_row_max) in (0,1] -> fp16-normal.
// accO rescaled by exp(m_old - m_new) per tile (flash-attention style).
// attn written in fixed exp(l-16) units (unnormalized); rescale kernel
// divides by rowsum afterwards (DRAM-roofline pass).
// QT=128 rows/CTA, 8 warps; each warp owns m16 x full n64 tile width, so
// row-max and rowsum are warp-local shuffles and there is NO cross-warp
// split-k reduction.

#define Bq 2
#define Hh 16
#define Ll 2048
#define Dd 128
#define QT 128
#define KTILE 64
#define NKT 32
#define NTHREADS 256
#define INV_SCALE 0.08838834764831845f   // 1/sqrt(128)
#define EXP_OFF 16.0f

// smem layout (bytes)
#define KPB 272                  // K tile row pitch (136 halfwords)
#define VPB 144                  // V^T plane row pitch (72 halfwords)
#define K_PLANE (64 * KPB)       // 17408 (fp16)
#define V_PLANE (128 * VPB)      // 18432 (fp16)
#define SM_STG 0
#define STG_V K_PLANE
#define STG_SIZE (K_PLANE + V_PLANE)     // 35840
#define SMEM_TOTAL (2 * STG_SIZE + 64)   // 71744

#define NELEM ((size_t)Bq * Hh * Ll * Dd)

__device__ __half g_Kh[NELEM];    // fp16 K
__device__ __half g_Vth[NELEM];   // fp16 V^T  [bh][d][k]
__device__ float g_inv[(size_t)Bq * Hh * Ll];

// ---------------- helpers ----------------
__device__ __forceinline__ uint32_t s2u(const void* p) {
    return (uint32_t)__cvta_generic_to_shared(p);
}
__device__ __forceinline__ void cp16(uint32_t dst, const void* src) {
    asm volatile("cp.async.cg.shared.global [%0], [%1], 16;\n" :: "r"(dst), "l"(src));
}
__device__ __forceinline__ void ldsm4(uint32_t r[4], uint32_t addr) {
    asm volatile("ldmatrix.sync.aligned.m8n8.x4.shared.b16 {%0,%1,%2,%3}, [%4];\n"
                 : "=r"(r[0]), "=r"(r[1]), "=r"(r[2]), "=r"(r[3]) : "r"(addr));
}
__device__ __forceinline__ void mma_f16(float c[4],
                                        uint32_t a0, uint32_t a1, uint32_t a2, uint32_t a3,
                                        uint32_t b0, uint32_t b1) {
    asm volatile(
        "mma.sync.aligned.m16n8k16.row.col.f32.f16.f16.f32 "
        "{%0,%1,%2,%3}, {%4,%5,%6,%7}, {%8,%9}, {%0,%1,%2,%3};\n"
        : "+f"(c[0]), "+f"(c[1]), "+f"(c[2]), "+f"(c[3])
        : "r"(a0), "r"(a1), "r"(a2), "r"(a3), "r"(b0), "r"(b1));
}
__device__ __forceinline__ uint32_t packh2(float x, float y) {
    __half hx = __float2half_rn(x);
    __half hy = __float2half_rn(y);
    return (uint32_t)*(unsigned short*)&hx | ((uint32_t)*(unsigned short*)&hy << 16);
}

// ---------------- prep kernels ----------------
__global__ void prep_k_kernel(const float* __restrict__ K) {
    size_t i = (size_t)blockIdx.x * blockDim.x + threadIdx.x;
    if (i >= NELEM / 4) return;
    float4 v = ((const float4*)K)[i];
    ((uint2*)g_Kh)[i] = make_uint2(packh2(v.x, v.y), packh2(v.z, v.w));
}

__global__ void prep_v_kernel(const float* __restrict__ V) {
    __shared__ float ts[32][33];
    const int tx = threadIdx.x, ty = threadIdx.y;    // (32, 8)
    const int k0 = blockIdx.x * 32;
    const int d0 = blockIdx.y * 32;
    const int bh = blockIdx.z;
    const size_t vb = (size_t)bh * Ll * Dd;
    #pragma unroll
    for (int i = 0; i < 4; ++i)
        ts[ty + 8 * i][tx] = V[vb + (size_t)(k0 + ty + 8 * i) * Dd + d0 + tx];
    __syncthreads();
    #pragma unroll
    for (int i = 0; i < 4; ++i) {
        float x = ts[tx][ty + 8 * i];
        size_t o = (size_t)bh * Dd * Ll + (size_t)(d0 + ty + 8 * i) * Ll + k0 + tx;
        g_Vth[o] = __float2half_rn(x);
    }
}

// ---------------- main kernel ----------------
__global__ void __launch_bounds__(NTHREADS, 1)
msrsa_flash_kernel(const float* __restrict__ Q,
                   const float* __restrict__ A,
                   const float* __restrict__ Dm,
                   const float* __restrict__ wA,
                   const float* __restrict__ wD,
                   float* __restrict__ out,
                   float* __restrict__ attn) {
    extern __shared__ char smc[];
    const uint32_t smb = s2u(smc);

    const int t = threadIdx.x;
    const int w = t >> 5;
    const int lane = t & 31;
    const int g = lane >> 2;
    const int tg = lane & 3;
    const int m0 = w * 16;        // this warp's 16 q rows

    const int bx = blockIdx.x;
    const int h = bx & (Hh - 1);
    const int qt = (bx >> 4) & 15;
    const int b = bx >> 8;
    const int q0 = qt * QT;
    const size_t bh = (size_t)(b * Hh + h);

    const float wa = wA[h];
    const float wd = wD[h];
    const size_t kbase = bh * (size_t)Ll * Dd;
    const size_t vbase = bh * (size_t)Dd * Ll;

    // ---- Q fragments in registers (loop-invariant, fp16) ----
    uint32_t qf[8][4];
    {
        const float* Qb = Q + (bh * Ll + q0 + m0) * Dd;
        #pragma unroll
        for (int s = 0; s < 8; ++s) {
            const int c0 = 16 * s + 2 * tg;
            float2 p0 = *(const float2*)&Qb[g * Dd + c0];
            float2 p1 = *(const float2*)&Qb[(g + 8) * Dd + c0];
            float2 p2 = *(const float2*)&Qb[g * Dd + c0 + 8];
            float2 p3 = *(const float2*)&Qb[(g + 8) * Dd + c0 + 8];
            qf[s][0] = packh2(p0.x, p0.y);
            qf[s][1] = packh2(p1.x, p1.y);
            qf[s][2] = packh2(p2.x, p2.y);
            qf[s][3] = packh2(p3.x, p3.y);
        }
    }

    // ---- stage issue (cp.async, one commit group per tile) ----
    auto issue_stage = [&](int kt, int buf) {
        const uint32_t sb = smb + SM_STG + buf * STG_SIZE;
        const char* gk = (const char*)(g_Kh + kbase + (size_t)kt * KTILE * Dd);
        #pragma unroll
        for (int j = 0; j < 4; ++j) {
            int idx = t + j * NTHREADS;          // 1024 chunks
            int row = idx >> 4, ch = idx & 15;
            cp16(sb + row * KPB + ch * 16, gk + row * 256 + ch * 16);
        }
        const char* gv = (const char*)(g_Vth + vbase) + (size_t)kt * 128;
        #pragma unroll
        for (int j = 0; j < 4; ++j) {
            int idx = t + j * NTHREADS;          // 1024 chunks
            int d = idx >> 3, ch = idx & 7;
            cp16(sb + STG_V + d * VPB + ch * 16, gv + (size_t)d * (Ll * 2) + ch * 16);
        }
        asm volatile("cp.async.commit_group;\n" ::: "memory");
    };

    // ldmatrix lane offsets (bytes)
    const uint32_t b_off = (uint32_t)((((lane >> 4) << 3) | (lane & 7)) * KPB
                                      + ((lane >> 3) & 1) * 16);
    const uint32_t v_off = (uint32_t)((((lane >> 4) << 3) | (lane & 7)) * VPB
                                      + ((lane >> 3) & 1) * 16);

    // per-thread global row pointers (rows m0+g and m0+g+8)
    const float* Ar = A  + ((size_t)b * Ll + q0 + m0 + g) * Ll;
    const float* Dr = Dm + ((size_t)b * Ll + q0 + m0 + g) * Ll;
    float* attn_r = attn + (bh * Ll + q0 + m0 + g) * Ll;

    float accO[16][4];
    #pragma unroll
    for (int i = 0; i < 16; ++i)
        #pragma unroll
        for (int j = 0; j < 4; ++j) accO[i][j] = 0.f;
    float rs_lo = 0.f, rs_hi = 0.f;
    float mr_lo = -1e30f, mr_hi = -1e30f;

    issue_stage(0, 0);

    for (int kt = 0; kt < NKT; ++kt) {
        asm volatile("cp.async.wait_group 0;\n" ::: "memory");
        __syncthreads();
        if (kt + 1 < NKT) issue_stage(kt + 1, (kt + 1) & 1);

        const uint32_t kh = smb + SM_STG + (kt & 1) * STG_SIZE;
        const uint32_t vhh = kh + STG_V;

        // ---- logits: m16 x n64 x d128, fp16 1-term ----
        float c[8][4];
        #pragma unroll
        for (int i = 0; i < 8; ++i)
            #pragma unroll
            for (int j = 0; j < 4; ++j) c[i][j] = 0.f;

        #pragma unroll
        for (int s = 0; s < 8; ++s) {
            #pragma unroll
            for (int nt = 0; nt < 4; ++nt) {
                uint32_t bf[4];
                ldsm4(bf, kh + b_off + nt * (16 * KPB) + s * 32);
                mma_f16(c[2 * nt],     qf[s][0], qf[s][1], qf[s][2], qf[s][3], bf[0], bf[1]);
                mma_f16(c[2 * nt + 1], qf[s][0], qf[s][1], qf[s][2], qf[s][3], bf[2], bf[3]);
            }
        }

        // ---- modulate ----
        #pragma unroll
        for (int j = 0; j < 8; ++j) {
            const int col = kt * KTILE + j * 8 + 2 * tg;
            float2 a0 = *(const float2*)(Ar + col);
            float2 d0 = *(const float2*)(Dr + col);
            float2 a1 = *(const float2*)(Ar + 8 * Ll + col);
            float2 d1 = *(const float2*)(Dr + 8 * Ll + col);
            c[j][0] *= (1.f + a0.x * wa + d0.x * wd) * INV_SCALE;
            c[j][1] *= (1.f + a0.y * wa + d0.y * wd) * INV_SCALE;
            c[j][2] *= (1.f + a1.x * wa + d1.x * wd) * INV_SCALE;
            c[j][3] *= (1.f + a1.y * wa + d1.y * wd) * INV_SCALE;
        }

        // ---- online row max (warp-local: shfl over tg lanes) ----
        float mt_lo = -1e30f, mt_hi = -1e30f;
        #pragma unroll
        for (int j = 0; j < 8; ++j) {
            mt_lo = fmaxf(mt_lo, fmaxf(c[j][0], c[j][1]));
            mt_hi = fmaxf(mt_hi, fmaxf(c[j][2], c[j][3]));
        }
        mt_lo = fmaxf(mt_lo, __shfl_xor_sync(0xffffffffu, mt_lo, 1));
        mt_lo = fmaxf(mt_lo, __shfl_xor_sync(0xffffffffu, mt_lo, 2));
        mt_hi = fmaxf(mt_hi, __shfl_xor_sync(0xffffffffu, mt_hi, 1));
        mt_hi = fmaxf(mt_hi, __shfl_xor_sync(0xffffffffu, mt_hi, 2));
        const float mn_lo = fmaxf(mr_lo, mt_lo);
        const float mn_hi = fmaxf(mr_hi, mt_hi);
        const float sc_lo = __expf(mr_lo - mn_lo);
        const float sc_hi = __expf(mr_hi - mn_hi);
        mr_lo = mn_lo;
        mr_hi = mn_hi;
        #pragma unroll
        for (int ni = 0; ni < 16; ++ni) {
            accO[ni][0] *= sc_lo; accO[ni][1] *= sc_lo;
            accO[ni][2] *= sc_hi; accO[ni][3] *= sc_hi;
        }
        const float sa_lo = __expf(mn_lo - EXP_OFF);   // exp(m-16): attn-unit scale
        const float sa_hi = __expf(mn_hi - EXP_OFF);

        // ---- exp + attn store + pack fp16 P fragments ----
        uint32_t pa[4][4];
        #pragma unroll
        for (int j = 0; j < 8; ++j) {
            const int col = kt * KTILE + j * 8 + 2 * tg;
            float p00 = __expf(c[j][0] - mn_lo);
            float p01 = __expf(c[j][1] - mn_lo);
            float p10 = __expf(c[j][2] - mn_hi);
            float p11 = __expf(c[j][3] - mn_hi);
            *(float2*)(attn_r + col) = make_float2(p00 * sa_lo, p01 * sa_lo);
            *(float2*)(attn_r + 8 * Ll + col) = make_float2(p10 * sa_hi, p11 * sa_hi);
            rs_lo += (p00 + p01) * sa_lo;
            rs_hi += (p10 + p11) * sa_hi;
            const int kf = j >> 1, half = j & 1;
            pa[kf][half * 2]     = packh2(p00, p01);
            pa[kf][half * 2 + 1] = packh2(p10, p11);
        }

        // ---- PV: A = P (m16 x k16 steps), B = V^T (k x d128), fp16 1-term ----
        #pragma unroll
        for (int kf = 0; kf < 4; ++kf) {
            #pragma unroll
            for (int dq = 0; dq < 8; ++dq) {
                uint32_t vb[4];
                ldsm4(vb, vhh + v_off + dq * (16 * VPB) + kf * 32);
                mma_f16(accO[dq * 2],     pa[kf][0], pa[kf][1], pa[kf][2], pa[kf][3], vb[0], vb[1]);
                mma_f16(accO[dq * 2 + 1], pa[kf][0], pa[kf][1], pa[kf][2], pa[kf][3], vb[2], vb[3]);
            }
        }
    }

    // ---- rowsum reduce (warp-local) + inverses ----
    rs_lo += __shfl_xor_sync(0xffffffffu, rs_lo, 1);
    rs_lo += __shfl_xor_sync(0xffffffffu, rs_lo, 2);
    rs_hi += __shfl_xor_sync(0xffffffffu, rs_hi, 1);
    rs_hi += __shfl_xor_sync(0xffffffffu, rs_hi, 2);
    if (tg == 0) {
        g_inv[bh * Ll + q0 + m0 + g] = 1.f / rs_lo;
        g_inv[bh * Ll + q0 + m0 + g + 8] = 1.f / rs_hi;
    }
    // out = accO * exp(m_final - 16) / rowsum
    const float inv_lo = __expf(mr_lo - EXP_OFF) / rs_lo;
    const float inv_hi = __expf(mr_hi - EXP_OFF) / rs_hi;

    // ---- write out (warp owns full rows; no cross-warp reduce) ----
    {
        float* olo = out + (bh * Ll + q0 + m0 + g) * Dd;
        #pragma unroll
        for (int ni = 0; ni < 16; ++ni) {
            const int col = ni * 8 + 2 * tg;
            *(float2*)(olo + col) = make_float2(accO[ni][0] * inv_lo,
                                                accO[ni][1] * inv_lo);
            *(float2*)(olo + 8 * Dd + col) = make_float2(accO[ni][2] * inv_hi,
                                                         accO[ni][3] * inv_hi);
        }
    }
}

// ---------------- rescale kernel (normalize attn) ----------------
__global__ void __launch_bounds__(256)
rescale_kernel(float* __restrict__ attn) {
    const size_t row = blockIdx.x;
    const float iv = g_inv[row];
    float4* p = (float4*)(attn + row * Ll);
    #pragma unroll
    for (int i = 0; i < 2; ++i) {
        int idx = threadIdx.x + i * 256;
        float4 v = p[idx];
        v.x *= iv; v.y *= iv; v.z *= iv; v.w *= iv;
        p[idx] = v;
    }
}

// ---------------- launch ----------------
extern "C" void kernel_launch(void* const* d_in, const int* in_sizes, int n_in,
                              void* d_out, int out_size) {
    (void)in_sizes; (void)n_in; (void)out_size;
    const float* Q  = (const float*)d_in[0];
    const float* K  = (const float*)d_in[1];
    const float* V  = (const float*)d_in[2];
    const float* A  = (const float*)d_in[3];
    const float* Ds = (const float*)d_in[4];
    const float* wA = (const float*)d_in[5];
    const float* wD = (const float*)d_in[6];

    float* out  = (float*)d_out;
    float* attn = (float*)d_out + (size_t)Bq * Hh * Ll * Dd;

    prep_k_kernel<<<(unsigned)(NELEM / 4 / 256), 256>>>(K);
    {
        dim3 gv(Ll / 32, Dd / 32, Bq * Hh);
        dim3 bv(32, 8);
        prep_v_kernel<<<gv, bv>>>(V);
    }

    cudaFuncSetAttribute(msrsa_flash_kernel,
                         cudaFuncAttributeMaxDynamicSharedMemorySize, SMEM_TOTAL);
    dim3 grid(Bq * Hh * (Ll / QT));   // 512 CTAs, h innermost
    msrsa_flash_kernel<<<grid, NTHREADS, SMEM_TOTAL>>>(Q, A, Ds, wA, wD, out, attn);

    rescale_kernel<<<Bq * Hh * Ll, 256>>>(attn);
}

// round 12
// speedup vs baseline: 2.1745x; 1.0847x over previous
#include <cuda_runtime.h>
#include <cuda_fp16.h>
#include <cuda_bf16.h>
#include <stdint.h>

// MSRSA fused attention — flash-style single-pass fp16 kernel, occupancy 2.
// B=2, H=16, L=2048, D=128.
// QK: fp16 1-term (Q frags in registers, K fp16).
// PV: fp16 1-term; P = exp(l - running_row_max) in (0,1] (flash online max).
// attn written in fixed exp(l-16) units; the CTA rescales its own attn
// block in place at the end (overlaps with the co-resident CTA at occ 2).
// QT=64 rows/CTA, 4 warps (128 threads); warp owns m16 x full n64 width ->
// row-max/rowsum are warp-local shuffles, no cross-warp split-k reduce.

#define Bq 2
#define Hh 16
#define Ll 2048
#define Dd 128
#define QT 64
#define KTILE 64
#define NKT 32
#define NTHREADS 128
#define INV_SCALE 0.08838834764831845f   // 1/sqrt(128)
#define EXP_OFF 16.0f

// smem layout (bytes)
#define KPB 272                  // K tile row pitch (136 halfwords)
#define VPB 144                  // V^T plane row pitch (72 halfwords)
#define K_PLANE (64 * KPB)       // 17408 (fp16)
#define V_PLANE (128 * VPB)      // 18432 (fp16)
#define SM_STG 0
#define STG_V K_PLANE
#define STG_SIZE (K_PLANE + V_PLANE)     // 35840
#define SM_INV (2 * STG_SIZE)            // 71680
#define SMEM_TOTAL (SM_INV + 256 + 16)   // 71952  (x2 CTAs = 143904 < 228KB)

#define NELEM ((size_t)Bq * Hh * Ll * Dd)

__device__ __half g_Kh[NELEM];    // fp16 K
__device__ __half g_Vth[NELEM];   // fp16 V^T  [bh][d][k]

// ---------------- helpers ----------------
__device__ __forceinline__ uint32_t s2u(const void* p) {
    return (uint32_t)__cvta_generic_to_shared(p);
}
__device__ __forceinline__ void cp16(uint32_t dst, const void* src) {
    asm volatile("cp.async.cg.shared.global [%0], [%1], 16;\n" :: "r"(dst), "l"(src));
}
__device__ __forceinline__ void ldsm4(uint32_t r[4], uint32_t addr) {
    asm volatile("ldmatrix.sync.aligned.m8n8.x4.shared.b16 {%0,%1,%2,%3}, [%4];\n"
                 : "=r"(r[0]), "=r"(r[1]), "=r"(r[2]), "=r"(r[3]) : "r"(addr));
}
__device__ __forceinline__ void mma_f16(float c[4],
                                        uint32_t a0, uint32_t a1, uint32_t a2, uint32_t a3,
                                        uint32_t b0, uint32_t b1) {
    asm volatile(
        "mma.sync.aligned.m16n8k16.row.col.f32.f16.f16.f32 "
        "{%0,%1,%2,%3}, {%4,%5,%6,%7}, {%8,%9}, {%0,%1,%2,%3};\n"
        : "+f"(c[0]), "+f"(c[1]), "+f"(c[2]), "+f"(c[3])
        : "r"(a0), "r"(a1), "r"(a2), "r"(a3), "r"(b0), "r"(b1));
}
__device__ __forceinline__ uint32_t packh2(float x, float y) {
    __half hx = __float2half_rn(x);
    __half hy = __float2half_rn(y);
    return (uint32_t)*(unsigned short*)&hx | ((uint32_t)*(unsigned short*)&hy << 16);
}

// ---------------- prep kernels ----------------
__global__ void prep_k_kernel(const float* __restrict__ K) {
    size_t i = (size_t)blockIdx.x * blockDim.x + threadIdx.x;
    if (i >= NELEM / 4) return;
    float4 v = ((const float4*)K)[i];
    ((uint2*)g_Kh)[i] = make_uint2(packh2(v.x, v.y), packh2(v.z, v.w));
}

__global__ void prep_v_kernel(const float* __restrict__ V) {
    __shared__ float ts[32][33];
    const int tx = threadIdx.x, ty = threadIdx.y;    // (32, 8)
    const int k0 = blockIdx.x * 32;
    const int d0 = blockIdx.y * 32;
    const int bh = blockIdx.z;
    const size_t vb = (size_t)bh * Ll * Dd;
    #pragma unroll
    for (int i = 0; i < 4; ++i)
        ts[ty + 8 * i][tx] = V[vb + (size_t)(k0 + ty + 8 * i) * Dd + d0 + tx];
    __syncthreads();
    #pragma unroll
    for (int i = 0; i < 4; ++i) {
        float x = ts[tx][ty + 8 * i];
        size_t o = (size_t)bh * Dd * Ll + (size_t)(d0 + ty + 8 * i) * Ll + k0 + tx;
        g_Vth[o] = __float2half_rn(x);
    }
}

// ---------------- main kernel ----------------
__global__ void __launch_bounds__(NTHREADS)
msrsa_flash_kernel(const float* __restrict__ Q,
                   const float* __restrict__ A,
                   const float* __restrict__ Dm,
                   const float* __restrict__ wA,
                   const float* __restrict__ wD,
                   float* __restrict__ out,
                   float* __restrict__ attn) {
    extern __shared__ char smc[];
    const uint32_t smb = s2u(smc);

    const int t = threadIdx.x;
    const int w = t >> 5;
    const int lane = t & 31;
    const int g = lane >> 2;
    const int tg = lane & 3;
    const int m0 = w * 16;        // this warp's 16 q rows

    const int bx = blockIdx.x;
    const int h = bx & (Hh - 1);
    const int qt = (bx >> 4) & 31;
    const int b = bx >> 9;
    const int q0 = qt * QT;
    const size_t bh = (size_t)(b * Hh + h);

    const float wa = wA[h];
    const float wd = wD[h];
    const size_t kbase = bh * (size_t)Ll * Dd;
    const size_t vbase = bh * (size_t)Dd * Ll;

    // ---- Q fragments in registers (loop-invariant, fp16) ----
    uint32_t qf[8][4];
    {
        const float* Qb = Q + (bh * Ll + q0 + m0) * Dd;
        #pragma unroll
        for (int s = 0; s < 8; ++s) {
            const int c0 = 16 * s + 2 * tg;
            float2 p0 = *(const float2*)&Qb[g * Dd + c0];
            float2 p1 = *(const float2*)&Qb[(g + 8) * Dd + c0];
            float2 p2 = *(const float2*)&Qb[g * Dd + c0 + 8];
            float2 p3 = *(const float2*)&Qb[(g + 8) * Dd + c0 + 8];
            qf[s][0] = packh2(p0.x, p0.y);
            qf[s][1] = packh2(p1.x, p1.y);
            qf[s][2] = packh2(p2.x, p2.y);
            qf[s][3] = packh2(p3.x, p3.y);
        }
    }

    // ---- stage issue (cp.async, one commit group per tile) ----
    auto issue_stage = [&](int kt, int buf) {
        const uint32_t sb = smb + SM_STG + buf * STG_SIZE;
        const char* gk = (const char*)(g_Kh + kbase + (size_t)kt * KTILE * Dd);
        #pragma unroll
        for (int j = 0; j < 8; ++j) {
            int idx = t + j * NTHREADS;          // 1024 chunks
            int row = idx >> 4, ch = idx & 15;
            cp16(sb + row * KPB + ch * 16, gk + row * 256 + ch * 16);
        }
        const char* gv = (const char*)(g_Vth + vbase) + (size_t)kt * 128;
        #pragma unroll
        for (int j = 0; j < 8; ++j) {
            int idx = t + j * NTHREADS;          // 1024 chunks
            int d = idx >> 3, ch = idx & 7;
            cp16(sb + STG_V + d * VPB + ch * 16, gv + (size_t)d * (Ll * 2) + ch * 16);
        }
        asm volatile("cp.async.commit_group;\n" ::: "memory");
    };

    // ldmatrix lane offsets (bytes)
    const uint32_t b_off = (uint32_t)((((lane >> 4) << 3) | (lane & 7)) * KPB
                                      + ((lane >> 3) & 1) * 16);
    const uint32_t v_off = (uint32_t)((((lane >> 4) << 3) | (lane & 7)) * VPB
                                      + ((lane >> 3) & 1) * 16);

    // per-thread global row pointers (rows m0+g and m0+g+8)
    const float* Ar = A  + ((size_t)b * Ll + q0 + m0 + g) * Ll;
    const float* Dr = Dm + ((size_t)b * Ll + q0 + m0 + g) * Ll;
    float* attn_r = attn + (bh * Ll + q0 + m0 + g) * Ll;

    float accO[16][4];
    #pragma unroll
    for (int i = 0; i < 16; ++i)
        #pragma unroll
        for (int j = 0; j < 4; ++j) accO[i][j] = 0.f;
    float rs_lo = 0.f, rs_hi = 0.f;
    float mr_lo = -1e30f, mr_hi = -1e30f;

    issue_stage(0, 0);

    for (int kt = 0; kt < NKT; ++kt) {
        asm volatile("cp.async.wait_group 0;\n" ::: "memory");
        __syncthreads();
        if (kt + 1 < NKT) issue_stage(kt + 1, (kt + 1) & 1);

        const uint32_t kh = smb + SM_STG + (kt & 1) * STG_SIZE;
        const uint32_t vhh = kh + STG_V;

        // ---- logits: m16 x n64 x d128, fp16 1-term ----
        float c[8][4];
        #pragma unroll
        for (int i = 0; i < 8; ++i)
            #pragma unroll
            for (int j = 0; j < 4; ++j) c[i][j] = 0.f;

        #pragma unroll
        for (int s = 0; s < 8; ++s) {
            #pragma unroll
            for (int nt = 0; nt < 4; ++nt) {
                uint32_t bf[4];
                ldsm4(bf, kh + b_off + nt * (16 * KPB) + s * 32);
                mma_f16(c[2 * nt],     qf[s][0], qf[s][1], qf[s][2], qf[s][3], bf[0], bf[1]);
                mma_f16(c[2 * nt + 1], qf[s][0], qf[s][1], qf[s][2], qf[s][3], bf[2], bf[3]);
            }
        }

        // ---- modulate ----
        #pragma unroll
        for (int j = 0; j < 8; ++j) {
            const int col = kt * KTILE + j * 8 + 2 * tg;
            float2 a0 = *(const float2*)(Ar + col);
            float2 d0 = *(const float2*)(Dr + col);
            float2 a1 = *(const float2*)(Ar + 8 * Ll + col);
            float2 d1 = *(const float2*)(Dr + 8 * Ll + col);
            c[j][0] *= (1.f + a0.x * wa + d0.x * wd) * INV_SCALE;
            c[j][1] *= (1.f + a0.y * wa + d0.y * wd) * INV_SCALE;
            c[j][2] *= (1.f + a1.x * wa + d1.x * wd) * INV_SCALE;
            c[j][3] *= (1.f + a1.y * wa + d1.y * wd) * INV_SCALE;
        }

        // ---- online row max (warp-local: shfl over tg lanes) ----
        float mt_lo = -1e30f, mt_hi = -1e30f;
        #pragma unroll
        for (int j = 0; j < 8; ++j) {
            mt_lo = fmaxf(mt_lo, fmaxf(c[j][0], c[j][1]));
            mt_hi = fmaxf(mt_hi, fmaxf(c[j][2], c[j][3]));
        }
        mt_lo = fmaxf(mt_lo, __shfl_xor_sync(0xffffffffu, mt_lo, 1));
        mt_lo = fmaxf(mt_lo, __shfl_xor_sync(0xffffffffu, mt_lo, 2));
        mt_hi = fmaxf(mt_hi, __shfl_xor_sync(0xffffffffu, mt_hi, 1));
        mt_hi = fmaxf(mt_hi, __shfl_xor_sync(0xffffffffu, mt_hi, 2));
        const float mn_lo = fmaxf(mr_lo, mt_lo);
        const float mn_hi = fmaxf(mr_hi, mt_hi);
        const float sc_lo = __expf(mr_lo - mn_lo);
        const float sc_hi = __expf(mr_hi - mn_hi);
        mr_lo = mn_lo;
        mr_hi = mn_hi;
        #pragma unroll
        for (int ni = 0; ni < 16; ++ni) {
            accO[ni][0] *= sc_lo; accO[ni][1] *= sc_lo;
            accO[ni][2] *= sc_hi; accO[ni][3] *= sc_hi;
        }
        const float sa_lo = __expf(mn_lo - EXP_OFF);   // exp(m-16): attn-unit scale
        const float sa_hi = __expf(mn_hi - EXP_OFF);

        // ---- exp + attn store + pack fp16 P fragments ----
        uint32_t pa[4][4];
        #pragma unroll
        for (int j = 0; j < 8; ++j) {
            const int col = kt * KTILE + j * 8 + 2 * tg;
            float p00 = __expf(c[j][0] - mn_lo);
            float p01 = __expf(c[j][1] - mn_lo);
            float p10 = __expf(c[j][2] - mn_hi);
            float p11 = __expf(c[j][3] - mn_hi);
            *(float2*)(attn_r + col) = make_float2(p00 * sa_lo, p01 * sa_lo);
            *(float2*)(attn_r + 8 * Ll + col) = make_float2(p10 * sa_hi, p11 * sa_hi);
            rs_lo += (p00 + p01) * sa_lo;
            rs_hi += (p10 + p11) * sa_hi;
            const int kf = j >> 1, half = j & 1;
            pa[kf][half * 2]     = packh2(p00, p01);
            pa[kf][half * 2 + 1] = packh2(p10, p11);
        }

        // ---- PV: A = P (m16 x k16 steps), B = V^T (k x d128), fp16 1-term ----
        #pragma unroll
        for (int kf = 0; kf < 4; ++kf) {
            #pragma unroll
            for (int dq = 0; dq < 8; ++dq) {
                uint32_t vb[4];
                ldsm4(vb, vhh + v_off + dq * (16 * VPB) + kf * 32);
                mma_f16(accO[dq * 2],     pa[kf][0], pa[kf][1], pa[kf][2], pa[kf][3], vb[0], vb[1]);
                mma_f16(accO[dq * 2 + 1], pa[kf][0], pa[kf][1], pa[kf][2], pa[kf][3], vb[2], vb[3]);
            }
        }
    }

    // ---- rowsum reduce (warp-local) + inverses ----
    rs_lo += __shfl_xor_sync(0xffffffffu, rs_lo, 1);
    rs_lo += __shfl_xor_sync(0xffffffffu, rs_lo, 2);
    rs_hi += __shfl_xor_sync(0xffffffffu, rs_hi, 1);
    rs_hi += __shfl_xor_sync(0xffffffffu, rs_hi, 2);

    float* sinv = (float*)(smc + SM_INV);
    if (tg == 0) {
        sinv[m0 + g] = 1.f / rs_lo;
        sinv[m0 + g + 8] = 1.f / rs_hi;
    }

    // out = accO * exp(m_final - 16) / rowsum
    const float inv_lo = __expf(mr_lo - EXP_OFF) / rs_lo;
    const float inv_hi = __expf(mr_hi - EXP_OFF) / rs_hi;

    // ---- write out (warp owns full rows; no cross-warp reduce) ----
    {
        float* olo = out + (bh * Ll + q0 + m0 + g) * Dd;
        #pragma unroll
        for (int ni = 0; ni < 16; ++ni) {
            const int col = ni * 8 + 2 * tg;
            *(float2*)(olo + col) = make_float2(accO[ni][0] * inv_lo,
                                                accO[ni][1] * inv_lo);
            *(float2*)(olo + 8 * Dd + col) = make_float2(accO[ni][2] * inv_hi,
                                                         accO[ni][3] * inv_hi);
        }
    }

    // ---- in-place attn rescale (overlaps with co-resident CTA at occ 2) ----
    __syncthreads();
    {
        float4* ab = (float4*)(attn + (bh * Ll + q0) * Ll);   // 64 rows x 512 float4
        #pragma unroll 8
        for (int i = 0; i < QT * Ll / 4 / NTHREADS; ++i) {
            const int idx = t + i * NTHREADS;
            const float iv = sinv[idx >> 9];
            float4 v = ab[idx];
            v.x *= iv; v.y *= iv; v.z *= iv; v.w *= iv;
            ab[idx] = v;
        }
    }
}

// ---------------- launch ----------------
extern "C" void kernel_launch(void* const* d_in, const int* in_sizes, int n_in,
                              void* d_out, int out_size) {
    (void)in_sizes; (void)n_in; (void)out_size;
    const float* Q  = (const float*)d_in[0];
    const float* K  = (const float*)d_in[1];
    const float* V  = (const float*)d_in[2];
    const float* A  = (const float*)d_in[3];
    const float* Ds = (const float*)d_in[4];
    const float* wA = (const float*)d_in[5];
    const float* wD = (const float*)d_in[6];

    float* out  = (float*)d_out;
    float* attn = (float*)d_out + (size_t)Bq * Hh * Ll * Dd;

    prep_k_kernel<<<(unsigned)(NELEM / 4 / 256), 256>>>(K);
    {
        dim3 gv(Ll / 32, Dd / 32, Bq * Hh);
        dim3 bv(32, 8);
        prep_v_kernel<<<gv, bv>>>(V);
    }

    cudaFuncSetAttribute(msrsa_flash_kernel,
                         cudaFuncAttributeMaxDynamicSharedMemorySize, SMEM_TOTAL);
    dim3 grid(Bq * Hh * (Ll / QT));   // 1024 CTAs, h innermost
    msrsa_flash_kernel<<<grid, NTHREADS, SMEM_TOTAL>>>(Q, A, Ds, wA, wD, out, attn);
}